// round 17
// baseline (speedup 1.0000x reference)
#include <cuda_runtime.h>

#define NT    128
#define GRID  740                  // 148 SMs x 5 blocks @ <=102 regs: one wave
#define TOTT  (GRID * NT)

__device__ double       g_acc;
__device__ unsigned int g_cnt;

__device__ __forceinline__ float frcp(float x) {
    float r; asm("rcp.approx.f32 %0, %1;" : "=f"(r) : "f"(x)); return r;
}

// 2-wide SoA lane pair: every op emits two independent instructions.
struct F2 { float a, b; };
__device__ __forceinline__ F2 bc(float v)            { return {v, v}; }
__device__ __forceinline__ F2 operator+(F2 x, F2 y)  { return {x.a + y.a, x.b + y.b}; }
__device__ __forceinline__ F2 operator-(F2 x, F2 y)  { return {x.a - y.a, x.b - y.b}; }
__device__ __forceinline__ F2 operator*(F2 x, F2 y)  { return {x.a * y.a, x.b * y.b}; }
__device__ __forceinline__ F2 operator-(F2 x)        { return {-x.a, -x.b}; }
__device__ __forceinline__ F2 fma2(F2 x, F2 y, F2 z) { return {fmaf(x.a, y.a, z.a), fmaf(x.b, y.b, z.b)}; }
__device__ __forceinline__ F2 min2(F2 x, F2 y)       { return {fminf(x.a, y.a), fminf(x.b, y.b)}; }
__device__ __forceinline__ F2 max2(F2 x, F2 y)       { return {fmaxf(x.a, y.a), fmaxf(x.b, y.b)}; }
__device__ __forceinline__ F2 sat2(F2 x)             { return {__saturatef(x.a), __saturatef(x.b)}; }
__device__ __forceinline__ F2 rcp2(F2 x)             { return {frcp(x.a), frcp(x.b)}; }
__device__ __forceinline__ F2 log2_(F2 x)            { return {__logf(x.a), __logf(x.b)}; }
__device__ __forceinline__ F2 abs2(F2 x)             { return {fabsf(x.a), fabsf(x.b)}; }

// Two independent box pairs, computed in lockstep.
__device__ __forceinline__ float pair_loss2(const float* __restrict__ pA,
                                            const float* __restrict__ qA,
                                            const float* __restrict__ pB,
                                            const float* __restrict__ qB) {
    F2 x1 = {pA[0], pB[0]}, y1 = {pA[1], pB[1]}, w1 = {pA[2], pB[2]};
    F2 h1 = {pA[3], pB[3]}, a1 = {pA[4], pB[4]};
    F2 x2 = {qA[0], qB[0]}, y2 = {qA[1], qB[1]}, w2 = {qA[2], qB[2]};
    F2 h2 = {qA[3], qB[3]}, a2 = {qA[4], qB[4]};

    // Box2 local frame, affine-normalized: clip region = [0,1]^2.
    F2 sf, cf, s2, c2;
    __sincosf(a1.a - a2.a, &sf.a, &cf.a);
    __sincosf(a1.b - a2.b, &sf.b, &cf.b);
    __sincosf(a2.a, &s2.a, &c2.a);
    __sincosf(a2.b, &s2.b, &c2.b);
    F2 ddx = x1 - x2, ddy = y1 - y2;
    F2 dxl = fma2(ddx, c2, ddy * s2);
    F2 dyl = fma2(-ddx, s2, ddy * c2);

    F2 iw = rcp2(w2), ih = rcp2(h2);
    F2 du = fma2(dxl, iw, bc(0.5f));
    F2 dv = fma2(dyl, ih, bc(0.5f));
    F2 hw1 = bc(0.5f) * w1, hh1 = bc(0.5f) * h1;
    F2 uxn = (hw1 * cf) * iw, uyn = (hw1 * sf) * ih;
    F2 vxn = -(hh1 * sf) * iw, vyn = (hh1 * cf) * ih;

    F2 Pu0 = du - uxn - vxn, Pv0 = dv - uyn - vyn;
    F2 Pu1 = du + uxn - vxn, Pv1 = dv + uyn - vyn;
    F2 Pu2 = du + uxn + vxn, Pv2 = dv + uyn + vyn;
    F2 Pu3 = du - uxn + vxn, Pv3 = dv - uyn + vyn;
    F2 au = uxn + uxn, av = uyn + uyn;
    F2 bu = vxn + vxn, bv = vyn + vyn;
    F2 iau = rcp2(au), iav = rcp2(av);
    F2 ibu = rcp2(bu), ibv = rcp2(bv);

    F2 acc0 = bc(0.0f), acc1 = bc(0.0f);
    F2 fu = bc(0.0f), fv = bc(0.0f), pu = bc(0.0f), pv = bc(0.0f);

    // Per original edge: u-window [t0,t1], v-window [slo,shi] in the same
    // t-parameter (shared reciprocals); 4 saturated emission points; connector
    // chords are boundary segments (zero net area on degeneracy).
    #pragma unroll
    for (int k = 0; k < 4; k++) {
        F2 cu  = (k == 0) ? Pu0 : (k == 1) ? Pu1 : (k == 2) ? Pu2 : Pu3;
        F2 cv  = (k == 0) ? Pv0 : (k == 1) ? Pv1 : (k == 2) ? Pv2 : Pv3;
        F2 ru  = (k == 0) ? au  : (k == 1) ? bu  : (k == 2) ? -au : -bu;
        F2 rv  = (k == 0) ? av  : (k == 1) ? bv  : (k == 2) ? -av : -bv;
        F2 iru = (k == 0) ? iau : (k == 1) ? ibu : (k == 2) ? -iau : -ibu;
        F2 irv = (k == 0) ? iav : (k == 1) ? ibv : (k == 2) ? -iav : -ibv;

        F2 tl = sat2(-cu * iru);
        F2 th = sat2(fma2(-cu, iru, iru));
        F2 t0 = min2(tl, th), t1 = max2(tl, th);

        F2 sv0 = -cv * irv;
        F2 sv1 = fma2(-cv, irv, irv);
        F2 slo = min2(sv0, sv1), shi = max2(sv0, sv1);

        F2 tA = max2(t0, slo);
        F2 tB = max2(min2(t1, shi), tA);

        F2 Au = sat2(fma2(t0, ru, cu)), Av = sat2(fma2(t0, rv, cv));
        F2 Bu = sat2(fma2(tA, ru, cu)), Bv = sat2(fma2(tA, rv, cv));
        F2 Cu = sat2(fma2(tB, ru, cu)), Cv = sat2(fma2(tB, rv, cv));
        F2 Du = sat2(fma2(t1, ru, cu)), Dv = sat2(fma2(t1, rv, cv));

        if (k == 0) { fu = Au; fv = Av; }
        else { acc0 = fma2(pu, Av, acc0); acc0 = fma2(-pv, Au, acc0); }
        acc1 = fma2(Au, Bv, acc1); acc1 = fma2(-Av, Bu, acc1);
        acc0 = fma2(Bu, Cv, acc0); acc0 = fma2(-Bv, Cu, acc0);
        acc1 = fma2(Cu, Dv, acc1); acc1 = fma2(-Cv, Du, acc1);
        pu = Du; pv = Dv;
    }
    acc0 = fma2(pu, fv, acc0);
    acc0 = fma2(-pv, fu, acc0);

    F2 A2 = w2 * h2, A1 = w1 * h1;
    F2 area = bc(0.5f) * abs2(acc0 + acc1) * A2;
    F2 den = max2(A1 + A2 - area, bc(1e-10f));
    // -log(clip(area/den, 1e-6)) == min(log(den)-log(area), -log(1e-6))
    F2 loss = min2(log2_(den) - log2_(area), bc(13.815511f));
    return loss.a + loss.b;
}

__global__ void __launch_bounds__(NT, 5)
k_loss(const float* __restrict__ pred, const float* __restrict__ tgt,
       float* __restrict__ out, int n) {
    __shared__ double ssum[NT / 32];

    const int tid  = threadIdx.x;
    const int half = (n + 1) >> 1;
    float loss = 0.0f;

    #pragma unroll 1
    for (int i = blockIdx.x * NT + tid; i < half; i += TOTT) {
        int j = i + half;
        bool valid = j < n;
        const float* pA = pred + (size_t)i * 5;
        const float* qA = tgt  + (size_t)i * 5;
        // Invalid lane-b: feed identical boxes (p==p) -> loss exactly 0.
        const float* pB = valid ? pred + (size_t)j * 5 : pA;
        const float* qB = valid ? tgt  + (size_t)j * 5 : pA;
        loss += pair_loss2(pA, qA, pB, qB);
    }

    // ---- block reduction ----
    #pragma unroll
    for (int o = 16; o > 0; o >>= 1)
        loss += __shfl_down_sync(0xFFFFFFFFu, loss, o);
    int lane = tid & 31, warp = tid >> 5;
    if (lane == 0) ssum[warp] = (double)loss;
    __syncthreads();

    if (tid == 0) {
        double t = 0.0;
        #pragma unroll
        for (int w = 0; w < NT / 32; w++) t += ssum[w];
        atomicAdd(&g_acc, t);
        __threadfence();
        unsigned int done = atomicAdd(&g_cnt, 1u);
        if (done == (unsigned int)(GRID - 1)) {
            double a = atomicAdd(&g_acc, 0.0);
            out[0] = (float)(a / (double)n);
            atomicExch((unsigned long long*)&g_acc, 0ull);
            atomicExch(&g_cnt, 0u);
        }
    }
}

extern "C" void kernel_launch(void* const* d_in, const int* in_sizes, int n_in,
                              void* d_out, int out_size) {
    const float* pred = (const float*)d_in[0];
    const float* tgt  = (const float*)d_in[1];
    int n = in_sizes[0] / 5;
    k_loss<<<GRID, NT>>>(pred, tgt, (float*)d_out, n);
}